// round 12
// baseline (speedup 1.0000x reference)
#include <cuda_runtime.h>
#include <cuda_fp16.h>
#include <math.h>
#include <stdint.h>

// Problem dims
#define Q    64
#define SQ   32
#define CC   256
#define SC   256
#define H    768
#define D    128
#define QT   31
#define CT   255
#define QROWS (Q*QT)     // 1984
#define CROWS (CC*CT)    // 65280
#define NROWS (QROWS+CROWS)

// Scratch
__device__ __half g_colh[(size_t)NROWS * D];
__device__ float  g_denom[Q];
__device__ int    g_idx[CC * 256];
__device__ int    g_cnt[CC];
__device__ float  g_cmax[CC];
__device__ int    g_qoff[Q + 1];
__device__ int    g_gqidx[QROWS];
__device__ int    g_tile_qs[16], g_tile_qe[16], g_tile_rs[16];
__device__ int    g_ntiles;
__device__ int    g_nun;            // ticket counter; reset by maxsim at sequence end
__device__ int    g_unrows[NROWS];

// ---------------------------------------------------------------------------
// helpers
// ---------------------------------------------------------------------------
__device__ __forceinline__ void mma_tf32(float* c, const uint32_t* a, const uint32_t* b) {
    asm volatile(
        "mma.sync.aligned.m16n8k8.row.col.f32.tf32.tf32.f32 "
        "{%0,%1,%2,%3},{%4,%5,%6,%7},{%8,%9},{%0,%1,%2,%3};\n"
        : "+f"(c[0]), "+f"(c[1]), "+f"(c[2]), "+f"(c[3])
        : "r"(a[0]), "r"(a[1]), "r"(a[2]), "r"(a[3]), "r"(b[0]), "r"(b[1]));
}
__device__ __forceinline__ void mma_f16(float* c, const uint32_t* a, const uint32_t* b) {
    asm volatile(
        "mma.sync.aligned.m16n8k16.row.col.f32.f16.f16.f32 "
        "{%0,%1,%2,%3},{%4,%5,%6,%7},{%8,%9},{%0,%1,%2,%3};\n"
        : "+f"(c[0]), "+f"(c[1]), "+f"(c[2]), "+f"(c[3])
        : "r"(a[0]), "r"(a[1]), "r"(a[2]), "r"(a[3]), "r"(b[0]), "r"(b[1]));
}
__device__ __forceinline__ uint32_t smem_u32(const void* p) {
    uint32_t a;
    asm("{ .reg .u64 t; cvta.to.shared.u64 t, %1; cvt.u32.u64 %0, t; }" : "=r"(a) : "l"(p));
    return a;
}
#define LDSM_X4(r0, r1, r2, r3, a) \
    asm volatile("ldmatrix.sync.aligned.m8n8.x4.shared.b16 {%0,%1,%2,%3}, [%4];" \
                 : "=r"(r0), "=r"(r1), "=r"(r2), "=r"(r3) : "r"(a))
#define LDSM_X2(r0, r1, a) \
    asm volatile("ldmatrix.sync.aligned.m8n8.x2.shared.b16 {%0,%1}, [%2];" \
                 : "=r"(r0), "=r"(r1) : "r"(a))
#define CP_ASYNC16(dst_u32, src_ptr) \
    asm volatile("cp.async.ca.shared.global [%0], [%1], 16;" :: "r"(dst_u32), "l"(src_ptr))
#define CP_COMMIT() asm volatile("cp.async.commit_group;" ::: "memory")
#define CP_WAIT1()  asm volatile("cp.async.wait_group 1;" ::: "memory")
#define CP_WAIT0()  asm volatile("cp.async.wait_group 0;" ::: "memory")

// ---------------------------------------------------------------------------
// Kernel 1: setup — pooled + unlist + compact + prep (role per blockIdx).
// ---------------------------------------------------------------------------
__global__ void setup_kernel(const float* __restrict__ qh,
                             const float* __restrict__ ch,
                             const float* __restrict__ bias,
                             const int*   __restrict__ qm,
                             const int*   __restrict__ cm,
                             float* __restrict__ out) {
    int b = blockIdx.x, t = threadIdx.x;
    int lane = t & 31, w = t >> 5;

    // ---- Role 1: pooled (fp32 exact) ----
    {
        __shared__ float red[8];
        const float* src;
        float mask;
        float* dst;
        if (b < Q) {
            src  = qh + (size_t)b * SQ * H;
            mask = (float)qm[b * SQ];
            dst  = out + Q * CC + (size_t)b * H;
        } else {
            int c = b - Q;
            src  = ch + (size_t)c * SC * H;
            mask = (float)cm[c * SC];
            dst  = out + Q * CC + Q * H + (size_t)c * H;
        }
        float v[3];
        float s = 0.f;
#pragma unroll
        for (int it = 0; it < 3; it++) {
            float x = src[t + it * 256] * mask;
            v[it] = x;
            s += x * x;
        }
#pragma unroll
        for (int o = 16; o; o >>= 1) s += __shfl_xor_sync(0xffffffffu, s, o);
        if (lane == 0) red[w] = s;
        __syncthreads();
        if (t < 8) {
            float ss = red[t];
#pragma unroll
            for (int o = 4; o; o >>= 1) ss += __shfl_xor_sync(0xffu, ss, o);
            if (t == 0) red[0] = ss;
        }
        __syncthreads();
        float inv = 1.f / fmaxf(sqrtf(red[0]), 1e-12f);
#pragma unroll
        for (int it = 0; it < 3; it++) dst[t + it * 256] = v[it] * inv;
        __syncthreads();
    }

    // ---- Role 2: unlist ----
    if (b < 263) {
        int r = b * 256 + t;
        int m = 0;
        if (r < NROWS) {
            if (r < QROWS) { int q = r / QT, i = r % QT; m = qm[q * SQ + i + 1]; }
            else { int rc = r - QROWS; int c = rc / CT, j = rc % CT; m = cm[c * SC + j + 1]; }
        }
        unsigned bal = __ballot_sync(0xffffffffu, m != 0);
        int cnt = __popc(bal);
        int pre = __popc(bal & ((1u << lane) - 1));
        int base = 0;
        if (lane == 0 && cnt) base = atomicAdd(&g_nun, cnt);
        base = __shfl_sync(0xffffffffu, base, 0);
        if (m) g_unrows[base + pre] = r;
    }

    // ---- Role 3: doc compaction + cvec rep-row write ----
    if (b < 256) {
        __shared__ int wcnt[8];
        __shared__ int firstmask;
        __shared__ float s_cr[4];
        int c = b;
        if (t == 0) firstmask = 1 << 30;
        __syncthreads();
        int valid = (t >= 1);
        int m = valid ? cm[c * SC + t] : 0;
        unsigned bal = __ballot_sync(0xffffffffu, m != 0);
        int pre = __popc(bal & ((1u << lane) - 1));
        if (lane == 0) wcnt[w] = __popc(bal);
        if (valid && !m) atomicMin(&firstmask, t);
        __syncthreads();
        int off = 0;
        for (int i = 0; i < w; i++) off += wcnt[i];
        if (valid && m) g_idx[c * 256 + off + pre] = t - 1;
        if (t == 0) {
            int total = 0;
            for (int i = 0; i < 8; i++) total += wcnt[i];
            if (firstmask < 256) { g_idx[c * 256 + total] = firstmask - 1; total++; }
            g_cnt[c] = total;
        }
        float v = (t < D) ? bias[t] : 0.f;
        float sq = v * v;
#pragma unroll
        for (int o = 16; o; o >>= 1) sq += __shfl_xor_sync(0xffffffffu, sq, o);
        if (lane == 0 && t < D) s_cr[w] = sq;
        __syncthreads();
        if (firstmask < 256 && t < D) {
            float tot = s_cr[0] + s_cr[1] + s_cr[2] + s_cr[3];
            float inv = 1.f / fmaxf(sqrtf(tot), 1e-12f);
            size_t row = (size_t)QROWS + (size_t)c * CT + (firstmask - 1);
            g_colh[row * D + t] = __float2half_rn(v * inv);
        }
    }

    // ---- Role 4: q-side prep ----
    if (b == 319) {
        __shared__ int s_nu[64];
        __shared__ int s_qoff[65];
        if (t < 64) {
            int nu = 0;
            for (int i = 1; i < SQ; i++) nu += (qm[t * SQ + i] != 0);
            s_nu[t] = nu;
            g_denom[t] = (float)nu;
        }
        __syncthreads();
        if (t == 0) {
            int acc = 0;
            for (int q = 0; q < 64; q++) { s_qoff[q] = acc; acc += s_nu[q]; }
            s_qoff[64] = acc;
            int ntiles = 0, cur = 0;
            while (cur < 64) {
                int qs = cur;
                while (cur < 64 && (s_qoff[cur + 1] - s_qoff[qs]) <= 128) cur++;
                g_tile_qs[ntiles] = qs;
                g_tile_qe[ntiles] = cur;
                g_tile_rs[ntiles] = s_qoff[qs];
                ntiles++;
            }
            g_ntiles = ntiles;
        }
        __syncthreads();
        if (t < 65) g_qoff[t] = s_qoff[t];
        if (t < 64) {
            int pos = s_qoff[t];
            for (int i = 1; i < SQ; i++)
                if (qm[t * SQ + i] != 0) g_gqidx[pos++] = t * QT + i - 1;
        }
    }
}

// ---------------------------------------------------------------------------
// Kernel 2: projection + l2norm over unmasked rows (unchanged from round 11).
// ---------------------------------------------------------------------------
#define P_SA 36
#define P_SW 132
#define P_AS_F (128 * P_SA)
#define P_WS_F (32 * P_SW)
#define P_SMEM_FLOATS (2*P_AS_F + 2*P_WS_F + 256 + 128 + 256 + 128 + 128)
#define P_SMEM_BYTES (P_SMEM_FLOATS * 4)

__global__ __launch_bounds__(256) void proj_kernel(const float* __restrict__ qh,
                                                   const float* __restrict__ ch,
                                                   const float* __restrict__ Wm,
                                                   const float* __restrict__ bias) {
    int nun = g_nun;
    if (blockIdx.x * 128 >= nun) return;

    extern __shared__ float psm[];
    float* As0 = psm;
    float* As1 = psm + P_AS_F;
    float* Ws0 = psm + 2 * P_AS_F;
    float* Ws1 = Ws0 + P_WS_F;
    const float** srcp = (const float**)(psm + 2 * P_AS_F + 2 * P_WS_F);
    int*   rowid  = (int*)(srcp + 128);
    float* rowsq  = (float*)(rowid + 128);
    float* invn   = rowsq + 256;
    float* s_bias = invn + 128;

    int t = threadIdx.x;
    int w = t >> 5, lane = t & 31, g = lane >> 2, tg = lane & 3;
    int mw = w & 3, nw = w >> 2;
    int m_warp = mw * 32, n_warp = nw * 64;

    if (t < 128) {
        s_bias[t] = bias[t];
        int idx = blockIdx.x * 128 + t;
        if (idx < nun) {
            int r = g_unrows[idx];
            rowid[t] = r;
            if (r < QROWS) {
                int q = r / QT, i = r % QT;
                srcp[t] = qh + (size_t)(q * SQ + i + 1) * H;
            } else {
                int rc = r - QROWS;
                int c = rc / CT, j = rc % CT;
                srcp[t] = ch + (size_t)(c * SC + j + 1) * H;
            }
        } else {
            rowid[t] = -1;
            srcp[t] = qh;
        }
    }
    __syncthreads();

#define PSTAGE(bufA, bufW, KT) do {                                             \
    _Pragma("unroll")                                                           \
    for (int itc = 0; itc < 4; itc++) {                                         \
        int idx = t + itc * 256;                                                \
        int m = idx >> 3, k4 = idx & 7;                                         \
        CP_ASYNC16(smem_u32((bufA) + m * P_SA + k4 * 4), srcp[m] + (KT) + k4 * 4); \
    }                                                                           \
    _Pragma("unroll")                                                           \
    for (int itc = 0; itc < 4; itc++) {                                         \
        int idx = t + itc * 256;                                                \
        int k = idx >> 5, d4 = idx & 31;                                        \
        CP_ASYNC16(smem_u32((bufW) + k * P_SW + d4 * 4),                        \
                   Wm + (size_t)((KT) + k) * D + d4 * 4);                       \
    }                                                                           \
} while (0)

    PSTAGE(As0, Ws0, 0);
    CP_COMMIT();

    float acc[2][8][4];
#pragma unroll
    for (int mt = 0; mt < 2; mt++)
#pragma unroll
        for (int nt4 = 0; nt4 < 8; nt4++)
#pragma unroll
            for (int i = 0; i < 4; i++) acc[mt][nt4][i] = 0.f;

    for (int it = 0; it < 24; it++) {
        if (it < 23) {
            if (it & 1) PSTAGE(As0, Ws0, (it + 1) * 32);
            else        PSTAGE(As1, Ws1, (it + 1) * 32);
            CP_COMMIT();
            CP_WAIT1();
        } else {
            CP_WAIT0();
        }
        __syncthreads();
        const float* A = (it & 1) ? As1 : As0;
        const float* W = (it & 1) ? Ws1 : Ws0;
#pragma unroll
        for (int ks = 0; ks < 4; ks++) {
            int k0 = ks * 8;
            uint32_t afr[2][4], bfr[8][2];
#pragma unroll
            for (int mt = 0; mt < 2; mt++) {
                int base = m_warp + mt * 16;
                afr[mt][0] = __float_as_uint(A[(base + g)     * P_SA + k0 + tg]);
                afr[mt][1] = __float_as_uint(A[(base + g + 8) * P_SA + k0 + tg]);
                afr[mt][2] = __float_as_uint(A[(base + g)     * P_SA + k0 + tg + 4]);
                afr[mt][3] = __float_as_uint(A[(base + g + 8) * P_SA + k0 + tg + 4]);
            }
#pragma unroll
            for (int nt4 = 0; nt4 < 8; nt4++) {
                int col = n_warp + nt4 * 8 + g;
                bfr[nt4][0] = __float_as_uint(W[(k0 + tg)     * P_SW + col]);
                bfr[nt4][1] = __float_as_uint(W[(k0 + tg + 4) * P_SW + col]);
            }
#pragma unroll
            for (int mt = 0; mt < 2; mt++)
#pragma unroll
                for (int nt4 = 0; nt4 < 8; nt4++)
                    mma_tf32(acc[mt][nt4], afr[mt], bfr[nt4]);
        }
        __syncthreads();
    }

#pragma unroll
    for (int mt = 0; mt < 2; mt++)
#pragma unroll
        for (int nt4 = 0; nt4 < 8; nt4++)
#pragma unroll
            for (int i = 0; i < 4; i++)
                acc[mt][nt4][i] += s_bias[n_warp + nt4 * 8 + 2 * tg + (i & 1)];

    float pr[2][2];
#pragma unroll
    for (int mt = 0; mt < 2; mt++)
#pragma unroll
        for (int h = 0; h < 2; h++) {
            float s = 0.f;
#pragma unroll
            for (int nt4 = 0; nt4 < 8; nt4++) {
                float c0 = acc[mt][nt4][2 * h], c1 = acc[mt][nt4][2 * h + 1];
                s += c0 * c0 + c1 * c1;
            }
            pr[mt][h] = s;
        }
#pragma unroll
    for (int off = 1; off <= 2; off <<= 1) {
#pragma unroll
        for (int mt = 0; mt < 2; mt++)
#pragma unroll
            for (int h = 0; h < 2; h++)
                pr[mt][h] += __shfl_xor_sync(0xffffffffu, pr[mt][h], off);
    }
    if (tg == 0) {
#pragma unroll
        for (int mt = 0; mt < 2; mt++)
#pragma unroll
            for (int h = 0; h < 2; h++)
                rowsq[(m_warp + mt * 16 + g + 8 * h) * 2 + nw] = pr[mt][h];
    }
    __syncthreads();
    if (t < 128) {
        float s = rowsq[t * 2] + rowsq[t * 2 + 1];
        invn[t] = 1.f / fmaxf(sqrtf(s), 1e-12f);
    }
    __syncthreads();

#pragma unroll
    for (int mt = 0; mt < 2; mt++)
#pragma unroll
        for (int h = 0; h < 2; h++) {
            int r = m_warp + mt * 16 + g + 8 * h;
            int grow = rowid[r];
            if (grow >= 0) {
                float inv = invn[r];
                __half* dst = g_colh + (size_t)grow * D;
#pragma unroll
                for (int nt4 = 0; nt4 < 8; nt4++) {
                    int col = n_warp + nt4 * 8 + 2 * tg;
                    *(__half2*)(dst + col) =
                        __floats2half2_rn(acc[mt][nt4][2 * h] * inv,
                                          acc[mt][nt4][2 * h + 1] * inv);
                }
            }
        }
#undef PSTAGE
}

// ---------------------------------------------------------------------------
// Kernel 3: cmax (unchanged)
// ---------------------------------------------------------------------------
__global__ void cmax_kernel(const float* __restrict__ bias) {
    int c = blockIdx.x, t = threadIdx.x;
    __shared__ float s_cv[D];
    __shared__ float s_cr[4];
    __shared__ float s_red2[8];
    float v = (t < D) ? bias[t] : 0.f;
    float sq = v * v;
#pragma unroll
    for (int o = 16; o; o >>= 1) sq += __shfl_xor_sync(0xffffffffu, sq, o);
    if ((t & 31) == 0 && t < D) s_cr[t >> 5] = sq;
    __syncthreads();
    if (t < D) {
        float tot = s_cr[0] + s_cr[1] + s_cr[2] + s_cr[3];
        s_cv[t] = v / fmaxf(sqrtf(tot), 1e-12f);
    }
    __syncthreads();
    int nc = g_cnt[c];
    float best = -INFINITY;
    for (int j = t; j < nc; j += 256) {
        size_t row = (size_t)QROWS + (size_t)c * CT + g_idx[c * 256 + j];
        const __half* col = g_colh + row * D;
        float s = 0.f;
#pragma unroll 4
        for (int k = 0; k < D; k++) s += s_cv[k] * __half2float(col[k]);
        best = fmaxf(best, s);
    }
#pragma unroll
    for (int o = 16; o; o >>= 1) best = fmaxf(best, __shfl_xor_sync(0xffffffffu, best, o));
    if ((t & 31) == 0) s_red2[t >> 5] = best;
    __syncthreads();
    if (t == 0) {
        float bmax = s_red2[0];
        for (int i = 1; i < 8; i++) bmax = fmaxf(bmax, s_red2[i]);
        g_cmax[c] = bmax;
    }
}

// ---------------------------------------------------------------------------
// Kernel 4: fused maxsim — ldmatrix fragment feeds, grid (256, 2).
// Block (c, yy): yy=0 tiles [0, ht), yy=1 tiles [ht, ntiles), ht=ceil(nt/2).
// B gathered once per block; A tiles cp.async-streamed, prefetch over epilogue.
// ---------------------------------------------------------------------------
#define MS_SAH 136
#define MS_SBH 136
#define MSA_HALFS (128 * MS_SAH)
#define MSB_HALFS (256 * MS_SBH)
#define MS_SMEM_BYTES ((MSA_HALFS + MSB_HALFS) * 2 + (8 * 128 + 128) * 4 + 256 * 4)

#define MS_STAGEA(TT_) do {                                                      \
    int rs_ = g_tile_rs[TT_];                                                    \
    int rows_ = g_qoff[g_tile_qe[TT_]] - rs_;                                    \
    int chunks_ = rows_ * 16;                                                    \
    _Pragma("unroll")                                                            \
    for (int j = 0; j < 4; j++) {                                                \
        int idx = t + j * 512;                                                   \
        if (idx < chunks_) {                                                     \
            int m = idx >> 4, k8 = idx & 15;                                     \
            int grow = g_gqidx[rs_ + m];                                         \
            CP_ASYNC16(smem_u32(&Ash[m * MS_SAH + k8 * 8]),                      \
                       g_colh + (size_t)grow * D + k8 * 8);                      \
        }                                                                        \
    }                                                                            \
} while (0)

template <int NT>
__device__ __forceinline__ void ms_body(__half* Ash, const __half* Bsh, float* red,
                                        float* rowmax, float* __restrict__ out,
                                        int t, int c, int tstart, int tend, int nc) {
    int w = t >> 5, lane = t & 31, g = lane >> 2, tg = lane & 3;
    int mw = w & 1, nw = w >> 1;
    int m_warp = mw * 64;

    // ldmatrix base addresses (loop-invariant; +k0*2 bytes per k-slice).
    // A (x4): lanes 0-15 -> rows base+0..15 @k0; lanes 16-31 -> same rows @k0+8.
    uint32_t a_base[4];
#pragma unroll
    for (int mt = 0; mt < 4; mt++)
        a_base[mt] = smem_u32(&Ash[(m_warp + mt * 16 + (lane & 15)) * MS_SAH
                                   + ((lane >> 4) << 3)]);
    // B pairs (x4): lanes 0-15 -> nt=2p rows @k0/k0+8; lanes 16-31 -> nt=2p+1.
    uint32_t b_base[(NT + 1) / 2];
#pragma unroll
    for (int p = 0; p < NT / 2; p++)
        b_base[p] = smem_u32((const __half*)&Bsh[((2 * p + (lane >> 4)) * 64 + nw * 8 + (lane & 7)) * MS_SBH
                                                 + (((lane >> 3) & 1) << 3)]);
    if (NT & 1)   // odd tail (x2): lanes 0-15 only
        b_base[NT / 2] = smem_u32((const __half*)&Bsh[((NT - 1) * 64 + nw * 8 + (lane & 7)) * MS_SBH
                                                      + (((lane >> 3) & 1) << 3)]);

    for (int tt = tstart; tt < tend; tt++) {
        CP_WAIT0();
        __syncthreads();

        float acc[4][NT][4];
#pragma unroll
        for (int mt = 0; mt < 4; mt++)
#pragma unroll
            for (int nt = 0; nt < NT; nt++)
#pragma unroll
                for (int k = 0; k < 4; k++) acc[mt][nt][k] = 0.f;

#pragma unroll
        for (int ks = 0; ks < 8; ks++) {
            int koff = ks * 32;                 // k0 * 2 bytes (k0 = ks*16)
            uint32_t afr[4][4], bfr[NT][2];
#pragma unroll
            for (int mt = 0; mt < 4; mt++)
                LDSM_X4(afr[mt][0], afr[mt][1], afr[mt][2], afr[mt][3],
                        a_base[mt] + koff);
#pragma unroll
            for (int p = 0; p < NT / 2; p++)
                LDSM_X4(bfr[2 * p][0], bfr[2 * p][1], bfr[2 * p + 1][0], bfr[2 * p + 1][1],
                        b_base[p] + koff);
            if (NT & 1)
                LDSM_X2(bfr[NT - 1][0], bfr[NT - 1][1], b_base[NT / 2] + koff);
#pragma unroll
            for (int mt = 0; mt < 4; mt++)
#pragma unroll
                for (int nt = 0; nt < NT; nt++)
                    mma_f16(acc[mt][nt], afr[mt], bfr[nt]);
        }

        // Row-max over compacted cols (guard j < nc).
        float rp[4][2];
#pragma unroll
        for (int mt = 0; mt < 4; mt++) { rp[mt][0] = -INFINITY; rp[mt][1] = -INFINITY; }
#pragma unroll
        for (int nt = 0; nt < NT; nt++)
#pragma unroll
            for (int mt = 0; mt < 4; mt++)
#pragma unroll
                for (int k = 0; k < 4; k++) {
                    int j = nt * 64 + nw * 8 + 2 * tg + (k & 1);
                    if (j < nc) rp[mt][k >> 1] = fmaxf(rp[mt][k >> 1], acc[mt][nt][k]);
                }
#pragma unroll
        for (int off = 1; off <= 2; off <<= 1)
#pragma unroll
            for (int mt = 0; mt < 4; mt++)
#pragma unroll
                for (int h = 0; h < 2; h++)
                    rp[mt][h] = fmaxf(rp[mt][h], __shfl_xor_sync(0xffffffffu, rp[mt][h], off));
        if (tg == 0) {
#pragma unroll
            for (int mt = 0; mt < 4; mt++)
#pragma unroll
                for (int h = 0; h < 2; h++)
                    red[nw * 128 + m_warp + mt * 16 + g + 8 * h] = rp[mt][h];
        }
        __syncthreads();

        // Prefetch next A tile — overlaps remaining epilogue.
        if (tt + 1 < tend) {
            MS_STAGEA(tt + 1);
            CP_COMMIT();
        }

        if (t < 128) {
            float mx = red[t];
#pragma unroll
            for (int r8 = 1; r8 < 8; r8++) mx = fmaxf(mx, red[r8 * 128 + t]);
            rowmax[t] = mx;
        }
        __syncthreads();

        if (t < 64) {
            int qs = g_tile_qs[tt], qe = g_tile_qe[tt];
            int qi = qs + t;
            if (qi < qe) {
                int rs = g_tile_rs[tt];
                int r0 = g_qoff[qi] - rs;
                int r1 = g_qoff[qi + 1] - rs;
                float s = 0.f;
                for (int r = r0; r < r1; r++) s += rowmax[r];
                float nu = g_denom[qi];
                out[qi * CC + c] = ((31.f - nu) * g_cmax[c] + s) / nu;
            }
        }
        __syncthreads();
    }
}

__global__ __launch_bounds__(512, 1) void maxsim_kernel(float* __restrict__ out) {
    if (blockIdx.x == 0 && blockIdx.y == 0 && threadIdx.x == 0) g_nun = 0;

    extern __shared__ char smc[];
    __half* Ash   = (__half*)smc;
    __half* Bsh   = Ash + MSA_HALFS;
    float* red    = (float*)(Bsh + MSB_HALFS);
    float* rowmax = red + 8 * 128;
    int*   sidx   = (int*)(rowmax + 128);

    int t  = threadIdx.x;
    int c  = blockIdx.x;
    int yy = blockIdx.y;

    int ntiles = g_ntiles;
    int ht = (ntiles + 1) >> 1;
    int tstart = yy ? ht : 0;
    int tend   = yy ? ntiles : ht;
    if (tstart >= tend) return;

    int nc = g_cnt[c];
    int NT = (nc + 63) >> 6;

    if (t < 256) sidx[t] = g_idx[c * 256 + t];
    __syncthreads();

    {
        const __half* base = g_colh + (size_t)(QROWS + c * CT) * D;
        int chunks = nc * 16;
#pragma unroll
        for (int j = 0; j < 8; j++) {
            int idx = t + j * 512;
            if (idx < chunks) {
                int n = idx >> 4, k8 = idx & 15;
                CP_ASYNC16(smem_u32(&Bsh[n * MS_SBH + k8 * 8]),
                           base + (size_t)sidx[n] * D + k8 * 8);
            }
        }
    }
    CP_COMMIT();

    MS_STAGEA(tstart);
    CP_COMMIT();

    if (NT == 2)      ms_body<2>(Ash, Bsh, red, rowmax, out, t, c, tstart, tend, nc);
    else if (NT == 3) ms_body<3>(Ash, Bsh, red, rowmax, out, t, c, tstart, tend, nc);
    else if (NT == 1) ms_body<1>(Ash, Bsh, red, rowmax, out, t, c, tstart, tend, nc);
    else              ms_body<4>(Ash, Bsh, red, rowmax, out, t, c, tstart, tend, nc);
}

// ---------------------------------------------------------------------------
extern "C" void kernel_launch(void* const* d_in, const int* in_sizes, int n_in,
                              void* d_out, int out_size) {
    const float* qh  = (const float*)d_in[0];
    const float* ch  = (const float*)d_in[1];
    const float* Wm  = (const float*)d_in[2];
    const float* bia = (const float*)d_in[3];
    const int*   qm  = (const int*)d_in[4];
    const int*   cm  = (const int*)d_in[5];
    float* out = (float*)d_out;

    cudaFuncSetAttribute(proj_kernel,
                         cudaFuncAttributeMaxDynamicSharedMemorySize,
                         P_SMEM_BYTES);
    cudaFuncSetAttribute(maxsim_kernel,
                         cudaFuncAttributeMaxDynamicSharedMemorySize,
                         MS_SMEM_BYTES);

    setup_kernel<<<320, 256>>>(qh, ch, bia, qm, cm, out);
    proj_kernel<<<(NROWS + 127) / 128, 256, P_SMEM_BYTES>>>(qh, ch, Wm, bia);
    cmax_kernel<<<CC, 256>>>(bia);
    maxsim_kernel<<<dim3(CC, 2), 512, MS_SMEM_BYTES>>>(out);
}

// round 13
// speedup vs baseline: 1.1243x; 1.1243x over previous
#include <cuda_runtime.h>
#include <cuda_fp16.h>
#include <math.h>
#include <stdint.h>

// Problem dims
#define Q    64
#define SQ   32
#define CC   256
#define SC   256
#define H    768
#define D    128
#define QT   31
#define CT   255
#define QROWS (Q*QT)     // 1984
#define CROWS (CC*CT)    // 65280
#define NROWS (QROWS+CROWS)

// Scratch
__device__ __half g_colh[(size_t)NROWS * D];
__device__ float  g_denom[Q];
__device__ int    g_idx[CC * 256];
__device__ int    g_cnt[CC];
__device__ int    g_qoff[Q + 1];
__device__ int    g_gqidx[QROWS];
__device__ int    g_tile_qs[16], g_tile_qe[16], g_tile_rs[16];
__device__ int    g_ntiles;
__device__ int    g_nun;            // ticket counter; reset by maxsim at sequence end
__device__ int    g_unrows[NROWS];

// ---------------------------------------------------------------------------
// helpers
// ---------------------------------------------------------------------------
__device__ __forceinline__ void mma_tf32(float* c, const uint32_t* a, const uint32_t* b) {
    asm volatile(
        "mma.sync.aligned.m16n8k8.row.col.f32.tf32.tf32.f32 "
        "{%0,%1,%2,%3},{%4,%5,%6,%7},{%8,%9},{%0,%1,%2,%3};\n"
        : "+f"(c[0]), "+f"(c[1]), "+f"(c[2]), "+f"(c[3])
        : "r"(a[0]), "r"(a[1]), "r"(a[2]), "r"(a[3]), "r"(b[0]), "r"(b[1]));
}
__device__ __forceinline__ void mma_f16(float* c, const uint32_t* a, const uint32_t* b) {
    asm volatile(
        "mma.sync.aligned.m16n8k16.row.col.f32.f16.f16.f32 "
        "{%0,%1,%2,%3},{%4,%5,%6,%7},{%8,%9},{%0,%1,%2,%3};\n"
        : "+f"(c[0]), "+f"(c[1]), "+f"(c[2]), "+f"(c[3])
        : "r"(a[0]), "r"(a[1]), "r"(a[2]), "r"(a[3]), "r"(b[0]), "r"(b[1]));
}
__device__ __forceinline__ uint32_t smem_u32(const void* p) {
    uint32_t a;
    asm("{ .reg .u64 t; cvta.to.shared.u64 t, %1; cvt.u32.u64 %0, t; }" : "=r"(a) : "l"(p));
    return a;
}
#define CP_ASYNC16(dst_u32, src_ptr) \
    asm volatile("cp.async.ca.shared.global [%0], [%1], 16;" :: "r"(dst_u32), "l"(src_ptr))
#define CP_COMMIT() asm volatile("cp.async.commit_group;" ::: "memory")
#define CP_WAIT1()  asm volatile("cp.async.wait_group 1;" ::: "memory")
#define CP_WAIT0()  asm volatile("cp.async.wait_group 0;" ::: "memory")

// ---------------------------------------------------------------------------
// Kernel 1: setup — pooled + unlist + compact + prep (role per blockIdx).
// ---------------------------------------------------------------------------
__global__ void setup_kernel(const float* __restrict__ qh,
                             const float* __restrict__ ch,
                             const float* __restrict__ bias,
                             const int*   __restrict__ qm,
                             const int*   __restrict__ cm,
                             float* __restrict__ out) {
    int b = blockIdx.x, t = threadIdx.x;
    int lane = t & 31, w = t >> 5;

    // ---- Role 1: pooled (fp32 exact) ----
    {
        __shared__ float red[8];
        const float* src;
        float mask;
        float* dst;
        if (b < Q) {
            src  = qh + (size_t)b * SQ * H;
            mask = (float)qm[b * SQ];
            dst  = out + Q * CC + (size_t)b * H;
        } else {
            int c = b - Q;
            src  = ch + (size_t)c * SC * H;
            mask = (float)cm[c * SC];
            dst  = out + Q * CC + Q * H + (size_t)c * H;
        }
        float v[3];
        float s = 0.f;
#pragma unroll
        for (int it = 0; it < 3; it++) {
            float x = src[t + it * 256] * mask;
            v[it] = x;
            s += x * x;
        }
#pragma unroll
        for (int o = 16; o; o >>= 1) s += __shfl_xor_sync(0xffffffffu, s, o);
        if (lane == 0) red[w] = s;
        __syncthreads();
        if (t < 8) {
            float ss = red[t];
#pragma unroll
            for (int o = 4; o; o >>= 1) ss += __shfl_xor_sync(0xffu, ss, o);
            if (t == 0) red[0] = ss;
        }
        __syncthreads();
        float inv = 1.f / fmaxf(sqrtf(red[0]), 1e-12f);
#pragma unroll
        for (int it = 0; it < 3; it++) dst[t + it * 256] = v[it] * inv;
        __syncthreads();
    }

    // ---- Role 2: unlist ----
    if (b < 263) {
        int r = b * 256 + t;
        int m = 0;
        if (r < NROWS) {
            if (r < QROWS) { int q = r / QT, i = r % QT; m = qm[q * SQ + i + 1]; }
            else { int rc = r - QROWS; int c = rc / CT, j = rc % CT; m = cm[c * SC + j + 1]; }
        }
        unsigned bal = __ballot_sync(0xffffffffu, m != 0);
        int cnt = __popc(bal);
        int pre = __popc(bal & ((1u << lane) - 1));
        int base = 0;
        if (lane == 0 && cnt) base = atomicAdd(&g_nun, cnt);
        base = __shfl_sync(0xffffffffu, base, 0);
        if (m) g_unrows[base + pre] = r;
    }

    // ---- Role 3: doc compaction + cvec rep-row write ----
    if (b < 256) {
        __shared__ int wcnt[8];
        __shared__ int firstmask;
        __shared__ float s_cr[4];
        int c = b;
        if (t == 0) firstmask = 1 << 30;
        __syncthreads();
        int valid = (t >= 1);
        int m = valid ? cm[c * SC + t] : 0;
        unsigned bal = __ballot_sync(0xffffffffu, m != 0);
        int pre = __popc(bal & ((1u << lane) - 1));
        if (lane == 0) wcnt[w] = __popc(bal);
        if (valid && !m) atomicMin(&firstmask, t);
        __syncthreads();
        int off = 0;
        for (int i = 0; i < w; i++) off += wcnt[i];
        if (valid && m) g_idx[c * 256 + off + pre] = t - 1;
        if (t == 0) {
            int total = 0;
            for (int i = 0; i < 8; i++) total += wcnt[i];
            if (firstmask < 256) { g_idx[c * 256 + total] = firstmask - 1; total++; }
            g_cnt[c] = total;
        }
        float v = (t < D) ? bias[t] : 0.f;
        float sq = v * v;
#pragma unroll
        for (int o = 16; o; o >>= 1) sq += __shfl_xor_sync(0xffffffffu, sq, o);
        if (lane == 0 && t < D) s_cr[w] = sq;
        __syncthreads();
        if (firstmask < 256 && t < D) {
            float tot = s_cr[0] + s_cr[1] + s_cr[2] + s_cr[3];
            float inv = 1.f / fmaxf(sqrtf(tot), 1e-12f);
            size_t row = (size_t)QROWS + (size_t)c * CT + (firstmask - 1);
            g_colh[row * D + t] = __float2half_rn(v * inv);
        }
    }

    // ---- Role 4: q-side prep ----
    if (b == 319) {
        __shared__ int s_nu[64];
        __shared__ int s_qoff[65];
        if (t < 64) {
            int nu = 0;
            for (int i = 1; i < SQ; i++) nu += (qm[t * SQ + i] != 0);
            s_nu[t] = nu;
            g_denom[t] = (float)nu;
        }
        __syncthreads();
        if (t == 0) {
            int acc = 0;
            for (int q = 0; q < 64; q++) { s_qoff[q] = acc; acc += s_nu[q]; }
            s_qoff[64] = acc;
            int ntiles = 0, cur = 0;
            while (cur < 64) {
                int qs = cur;
                while (cur < 64 && (s_qoff[cur + 1] - s_qoff[qs]) <= 128) cur++;
                g_tile_qs[ntiles] = qs;
                g_tile_qe[ntiles] = cur;
                g_tile_rs[ntiles] = s_qoff[qs];
                ntiles++;
            }
            g_ntiles = ntiles;
        }
        __syncthreads();
        if (t < 65) g_qoff[t] = s_qoff[t];
        if (t < 64) {
            int pos = s_qoff[t];
            for (int i = 1; i < SQ; i++)
                if (qm[t * SQ + i] != 0) g_gqidx[pos++] = t * QT + i - 1;
        }
    }
}

// ---------------------------------------------------------------------------
// Kernel 2: projection + l2norm over unmasked rows (unchanged from round 11).
// ---------------------------------------------------------------------------
#define P_SA 36
#define P_SW 132
#define P_AS_F (128 * P_SA)
#define P_WS_F (32 * P_SW)
#define P_SMEM_FLOATS (2*P_AS_F + 2*P_WS_F + 256 + 128 + 256 + 128 + 128)
#define P_SMEM_BYTES (P_SMEM_FLOATS * 4)

__global__ __launch_bounds__(256) void proj_kernel(const float* __restrict__ qh,
                                                   const float* __restrict__ ch,
                                                   const float* __restrict__ Wm,
                                                   const float* __restrict__ bias) {
    int nun = g_nun;
    if (blockIdx.x * 128 >= nun) return;

    extern __shared__ float psm[];
    float* As0 = psm;
    float* As1 = psm + P_AS_F;
    float* Ws0 = psm + 2 * P_AS_F;
    float* Ws1 = Ws0 + P_WS_F;
    const float** srcp = (const float**)(psm + 2 * P_AS_F + 2 * P_WS_F);
    int*   rowid  = (int*)(srcp + 128);
    float* rowsq  = (float*)(rowid + 128);
    float* invn   = rowsq + 256;
    float* s_bias = invn + 128;

    int t = threadIdx.x;
    int w = t >> 5, lane = t & 31, g = lane >> 2, tg = lane & 3;
    int mw = w & 3, nw = w >> 2;
    int m_warp = mw * 32, n_warp = nw * 64;

    if (t < 128) {
        s_bias[t] = bias[t];
        int idx = blockIdx.x * 128 + t;
        if (idx < nun) {
            int r = g_unrows[idx];
            rowid[t] = r;
            if (r < QROWS) {
                int q = r / QT, i = r % QT;
                srcp[t] = qh + (size_t)(q * SQ + i + 1) * H;
            } else {
                int rc = r - QROWS;
                int c = rc / CT, j = rc % CT;
                srcp[t] = ch + (size_t)(c * SC + j + 1) * H;
            }
        } else {
            rowid[t] = -1;
            srcp[t] = qh;
        }
    }
    __syncthreads();

#define PSTAGE(bufA, bufW, KT) do {                                             \
    _Pragma("unroll")                                                           \
    for (int itc = 0; itc < 4; itc++) {                                         \
        int idx = t + itc * 256;                                                \
        int m = idx >> 3, k4 = idx & 7;                                         \
        CP_ASYNC16(smem_u32((bufA) + m * P_SA + k4 * 4), srcp[m] + (KT) + k4 * 4); \
    }                                                                           \
    _Pragma("unroll")                                                           \
    for (int itc = 0; itc < 4; itc++) {                                         \
        int idx = t + itc * 256;                                                \
        int k = idx >> 5, d4 = idx & 31;                                        \
        CP_ASYNC16(smem_u32((bufW) + k * P_SW + d4 * 4),                        \
                   Wm + (size_t)((KT) + k) * D + d4 * 4);                       \
    }                                                                           \
} while (0)

    PSTAGE(As0, Ws0, 0);
    CP_COMMIT();

    float acc[2][8][4];
#pragma unroll
    for (int mt = 0; mt < 2; mt++)
#pragma unroll
        for (int nt4 = 0; nt4 < 8; nt4++)
#pragma unroll
            for (int i = 0; i < 4; i++) acc[mt][nt4][i] = 0.f;

    for (int it = 0; it < 24; it++) {
        if (it < 23) {
            if (it & 1) PSTAGE(As0, Ws0, (it + 1) * 32);
            else        PSTAGE(As1, Ws1, (it + 1) * 32);
            CP_COMMIT();
            CP_WAIT1();
        } else {
            CP_WAIT0();
        }
        __syncthreads();
        const float* A = (it & 1) ? As1 : As0;
        const float* W = (it & 1) ? Ws1 : Ws0;
#pragma unroll
        for (int ks = 0; ks < 4; ks++) {
            int k0 = ks * 8;
            uint32_t afr[2][4], bfr[8][2];
#pragma unroll
            for (int mt = 0; mt < 2; mt++) {
                int base = m_warp + mt * 16;
                afr[mt][0] = __float_as_uint(A[(base + g)     * P_SA + k0 + tg]);
                afr[mt][1] = __float_as_uint(A[(base + g + 8) * P_SA + k0 + tg]);
                afr[mt][2] = __float_as_uint(A[(base + g)     * P_SA + k0 + tg + 4]);
                afr[mt][3] = __float_as_uint(A[(base + g + 8) * P_SA + k0 + tg + 4]);
            }
#pragma unroll
            for (int nt4 = 0; nt4 < 8; nt4++) {
                int col = n_warp + nt4 * 8 + g;
                bfr[nt4][0] = __float_as_uint(W[(k0 + tg)     * P_SW + col]);
                bfr[nt4][1] = __float_as_uint(W[(k0 + tg + 4) * P_SW + col]);
            }
#pragma unroll
            for (int mt = 0; mt < 2; mt++)
#pragma unroll
                for (int nt4 = 0; nt4 < 8; nt4++)
                    mma_tf32(acc[mt][nt4], afr[mt], bfr[nt4]);
        }
        __syncthreads();
    }

#pragma unroll
    for (int mt = 0; mt < 2; mt++)
#pragma unroll
        for (int nt4 = 0; nt4 < 8; nt4++)
#pragma unroll
            for (int i = 0; i < 4; i++)
                acc[mt][nt4][i] += s_bias[n_warp + nt4 * 8 + 2 * tg + (i & 1)];

    float pr[2][2];
#pragma unroll
    for (int mt = 0; mt < 2; mt++)
#pragma unroll
        for (int h = 0; h < 2; h++) {
            float s = 0.f;
#pragma unroll
            for (int nt4 = 0; nt4 < 8; nt4++) {
                float c0 = acc[mt][nt4][2 * h], c1 = acc[mt][nt4][2 * h + 1];
                s += c0 * c0 + c1 * c1;
            }
            pr[mt][h] = s;
        }
#pragma unroll
    for (int off = 1; off <= 2; off <<= 1) {
#pragma unroll
        for (int mt = 0; mt < 2; mt++)
#pragma unroll
            for (int h = 0; h < 2; h++)
                pr[mt][h] += __shfl_xor_sync(0xffffffffu, pr[mt][h], off);
    }
    if (tg == 0) {
#pragma unroll
        for (int mt = 0; mt < 2; mt++)
#pragma unroll
            for (int h = 0; h < 2; h++)
                rowsq[(m_warp + mt * 16 + g + 8 * h) * 2 + nw] = pr[mt][h];
    }
    __syncthreads();
    if (t < 128) {
        float s = rowsq[t * 2] + rowsq[t * 2 + 1];
        invn[t] = 1.f / fmaxf(sqrtf(s), 1e-12f);
    }
    __syncthreads();

#pragma unroll
    for (int mt = 0; mt < 2; mt++)
#pragma unroll
        for (int h = 0; h < 2; h++) {
            int r = m_warp + mt * 16 + g + 8 * h;
            int grow = rowid[r];
            if (grow >= 0) {
                float inv = invn[r];
                __half* dst = g_colh + (size_t)grow * D;
#pragma unroll
                for (int nt4 = 0; nt4 < 8; nt4++) {
                    int col = n_warp + nt4 * 8 + 2 * tg;
                    *(__half2*)(dst + col) =
                        __floats2half2_rn(acc[mt][nt4][2 * h] * inv,
                                          acc[mt][nt4][2 * h + 1] * inv);
                }
            }
        }
#undef PSTAGE
}

// ---------------------------------------------------------------------------
// Kernel 3: fused maxsim — round-11 body (scalar LDS frags, proven 61.8us)
// + IN-BLOCK cmax (uses the B tile already in smem; drops the cmax kernel).
// Grid (256, 4), 512 threads (16 warps = 2Mx8N).
// ---------------------------------------------------------------------------
#define MS_SAH 136
#define MS_SBH 136
#define MSA_HALFS (128 * MS_SAH)
#define MSB_HALFS (256 * MS_SBH)
#define MS_SMEM_BYTES ((MSA_HALFS + MSB_HALFS) * 2 + (8 * 128 + 128) * 4 + 256 * 4 + (128 + 32) * 4)

#define MS_STAGEA(TT_) do {                                                      \
    int rs_ = g_tile_rs[TT_];                                                    \
    int rows_ = g_qoff[g_tile_qe[TT_]] - rs_;                                    \
    int chunks_ = rows_ * 16;                                                    \
    _Pragma("unroll")                                                            \
    for (int j = 0; j < 4; j++) {                                                \
        int idx = t + j * 512;                                                   \
        if (idx < chunks_) {                                                     \
            int m = idx >> 4, k8 = idx & 15;                                     \
            int grow = g_gqidx[rs_ + m];                                         \
            CP_ASYNC16(smem_u32(&Ash[m * MS_SAH + k8 * 8]),                      \
                       g_colh + (size_t)grow * D + k8 * 8);                      \
        }                                                                        \
    }                                                                            \
} while (0)

template <int NT>
__device__ __forceinline__ void ms_body(__half* Ash, const __half* Bsh, float* red,
                                        float* rowmax, const float* s_cv,
                                        float* s_cm, float* __restrict__ out,
                                        int t, int c, int yy, int nc, int ntiles) {
    int w = t >> 5, lane = t & 31, g = lane >> 2, tg = lane & 3;
    int mw = w & 1, nw = w >> 1;
    int m_warp = mw * 64;

    // ---- In-block cmax: max_j dot(cvec, B_j) using the gathered B tile. ----
    CP_WAIT0();          // B (and first A) landed
    __syncthreads();
    {
        int j = t >> 1, kh = t & 1;
        float p = 0.f;
        if (j < nc) {
            const __half* row = Bsh + j * MS_SBH + kh * 64;
            const float* cv = s_cv + kh * 64;
#pragma unroll 8
            for (int k = 0; k < 64; k += 2) {
                __half2 h2 = *(const __half2*)(row + k);
                float2 f2 = __half22float2(h2);
                p += cv[k] * f2.x + cv[k + 1] * f2.y;
            }
        }
        p += __shfl_xor_sync(0xffffffffu, p, 1);         // full dot in both lanes
        float mj = (j < nc) ? p : -INFINITY;
#pragma unroll
        for (int o = 16; o >= 2; o >>= 1)
            mj = fmaxf(mj, __shfl_xor_sync(0xffffffffu, mj, o));
        if (lane == 0) s_cm[1 + w] = mj;                 // per-warp max
    }
    __syncthreads();
    if (t == 0) {
        float b = s_cm[1];
        for (int i = 2; i <= 16; i++) b = fmaxf(b, s_cm[i]);
        s_cm[0] = b;
    }
    __syncthreads();
    float cmax = s_cm[0];

    for (int i = 0; i < 4; i++) {
        int tt = yy * 4 + i;
        if (tt >= ntiles) break;
        CP_WAIT0();
        __syncthreads();

        float acc[4][NT][4];
#pragma unroll
        for (int mt = 0; mt < 4; mt++)
#pragma unroll
            for (int nt = 0; nt < NT; nt++)
#pragma unroll
                for (int k = 0; k < 4; k++) acc[mt][nt][k] = 0.f;

#pragma unroll
        for (int ks = 0; ks < 8; ks++) {
            int k0 = ks * 16;
            uint32_t afr[4][4], bfr[NT][2];
#pragma unroll
            for (int mt = 0; mt < 4; mt++) {
                int base = m_warp + mt * 16;
                afr[mt][0] = *(const uint32_t*)&Ash[(base + g)     * MS_SAH + k0 + 2 * tg];
                afr[mt][1] = *(const uint32_t*)&Ash[(base + g + 8) * MS_SAH + k0 + 2 * tg];
                afr[mt][2] = *(const uint32_t*)&Ash[(base + g)     * MS_SAH + k0 + 2 * tg + 8];
                afr[mt][3] = *(const uint32_t*)&Ash[(base + g + 8) * MS_SAH + k0 + 2 * tg + 8];
            }
#pragma unroll
            for (int nt = 0; nt < NT; nt++) {
                int n = nt * 64 + nw * 8 + g;
                bfr[nt][0] = *(const uint32_t*)&Bsh[n * MS_SBH + k0 + 2 * tg];
                bfr[nt][1] = *(const uint32_t*)&Bsh[n * MS_SBH + k0 + 2 * tg + 8];
            }
#pragma unroll
            for (int mt = 0; mt < 4; mt++)
#pragma unroll
                for (int nt = 0; nt < NT; nt++)
                    mma_f16(acc[mt][nt], afr[mt], bfr[nt]);
        }

        float rp[4][2];
#pragma unroll
        for (int mt = 0; mt < 4; mt++) { rp[mt][0] = -INFINITY; rp[mt][1] = -INFINITY; }
#pragma unroll
        for (int nt = 0; nt < NT; nt++)
#pragma unroll
            for (int mt = 0; mt < 4; mt++)
#pragma unroll
                for (int k = 0; k < 4; k++) {
                    int j = nt * 64 + nw * 8 + 2 * tg + (k & 1);
                    if (j < nc) rp[mt][k >> 1] = fmaxf(rp[mt][k >> 1], acc[mt][nt][k]);
                }
#pragma unroll
        for (int off = 1; off <= 2; off <<= 1)
#pragma unroll
            for (int mt = 0; mt < 4; mt++)
#pragma unroll
                for (int h = 0; h < 2; h++)
                    rp[mt][h] = fmaxf(rp[mt][h], __shfl_xor_sync(0xffffffffu, rp[mt][h], off));
        if (tg == 0) {
#pragma unroll
            for (int mt = 0; mt < 4; mt++)
#pragma unroll
                for (int h = 0; h < 2; h++)
                    red[nw * 128 + m_warp + mt * 16 + g + 8 * h] = rp[mt][h];
        }
        __syncthreads();

        if (i < 3 && tt + 1 < ntiles) {
            MS_STAGEA(tt + 1);
            CP_COMMIT();
        }

        if (t < 128) {
            float mx = red[t];
#pragma unroll
            for (int r8 = 1; r8 < 8; r8++) mx = fmaxf(mx, red[r8 * 128 + t]);
            rowmax[t] = mx;
        }
        __syncthreads();

        if (t < 64) {
            int qs = g_tile_qs[tt], qe = g_tile_qe[tt];
            int qi = qs + t;
            if (qi < qe) {
                int rs = g_tile_rs[tt];
                int r0 = g_qoff[qi] - rs;
                int r1 = g_qoff[qi + 1] - rs;
                float s = 0.f;
                for (int r = r0; r < r1; r++) s += rowmax[r];
                float nu = g_denom[qi];
                out[qi * CC + c] = ((31.f - nu) * cmax + s) / nu;
            }
        }
        __syncthreads();
    }
}

__global__ __launch_bounds__(512, 1) void maxsim_kernel(const float* __restrict__ bias,
                                                        float* __restrict__ out) {
    if (blockIdx.x == 0 && blockIdx.y == 0 && threadIdx.x == 0) g_nun = 0;

    extern __shared__ char smc[];
    __half* Ash   = (__half*)smc;
    __half* Bsh   = Ash + MSA_HALFS;
    float* red    = (float*)(Bsh + MSB_HALFS);
    float* rowmax = red + 8 * 128;
    int*   sidx   = (int*)(rowmax + 128);
    float* s_cv   = (float*)(sidx + 256);      // [128] cvec fp32
    float* s_cm   = s_cv + 128;                // [32] cmax scratch (s_cm[0] = result)

    int t  = threadIdx.x;
    int c  = blockIdx.x;
    int yy = blockIdx.y;

    int ntiles = g_ntiles;
    if (yy * 4 >= ntiles) return;

    int nc = g_cnt[c];
    int NT = (nc + 63) >> 6;

    if (t < 256) sidx[t] = g_idx[c * 256 + t];
    // cvec (fp32) from bias — matches old cmax_kernel numerics.
    {
        __shared__ float s_cr[4];
        float v = (t < D) ? bias[t] : 0.f;
        float sq = v * v;
#pragma unroll
        for (int o = 16; o; o >>= 1) sq += __shfl_xor_sync(0xffffffffu, sq, o);
        if ((t & 31) == 0 && t < D) s_cr[t >> 5] = sq;
        __syncthreads();
        if (t < D) {
            float tot = s_cr[0] + s_cr[1] + s_cr[2] + s_cr[3];
            s_cv[t] = v / fmaxf(sqrtf(tot), 1e-12f);
        }
    }
    __syncthreads();

    {
        const __half* base = g_colh + (size_t)(QROWS + c * CT) * D;
        int chunks = nc * 16;
#pragma unroll
        for (int j = 0; j < 8; j++) {
            int idx = t + j * 512;
            if (idx < chunks) {
                int n = idx >> 4, k8 = idx & 15;
                CP_ASYNC16(smem_u32(&Bsh[n * MS_SBH + k8 * 8]),
                           base + (size_t)sidx[n] * D + k8 * 8);
            }
        }
    }
    CP_COMMIT();

    MS_STAGEA(yy * 4);
    CP_COMMIT();

    if (NT == 2)      ms_body<2>(Ash, Bsh, red, rowmax, s_cv, s_cm, out, t, c, yy, nc, ntiles);
    else if (NT == 3) ms_body<3>(Ash, Bsh, red, rowmax, s_cv, s_cm, out, t, c, yy, nc, ntiles);
    else if (NT == 1) ms_body<1>(Ash, Bsh, red, rowmax, s_cv, s_cm, out, t, c, yy, nc, ntiles);
    else              ms_body<4>(Ash, Bsh, red, rowmax, s_cv, s_cm, out, t, c, yy, nc, ntiles);
}

// ---------------------------------------------------------------------------
extern "C" void kernel_launch(void* const* d_in, const int* in_sizes, int n_in,
                              void* d_out, int out_size) {
    const float* qh  = (const float*)d_in[0];
    const float* ch  = (const float*)d_in[1];
    const float* Wm  = (const float*)d_in[2];
    const float* bia = (const float*)d_in[3];
    const int*   qm  = (const int*)d_in[4];
    const int*   cm  = (const int*)d_in[5];
    float* out = (float*)d_out;

    cudaFuncSetAttribute(proj_kernel,
                         cudaFuncAttributeMaxDynamicSharedMemorySize,
                         P_SMEM_BYTES);
    cudaFuncSetAttribute(maxsim_kernel,
                         cudaFuncAttributeMaxDynamicSharedMemorySize,
                         MS_SMEM_BYTES);

    setup_kernel<<<320, 256>>>(qh, ch, bia, qm, cm, out);
    proj_kernel<<<(NROWS + 127) / 128, 256, P_SMEM_BYTES>>>(qh, ch, Wm, bia);
    maxsim_kernel<<<dim3(CC, 4), 512, MS_SMEM_BYTES>>>(bia, out);
}

// round 14
// speedup vs baseline: 1.1601x; 1.0319x over previous
#include <cuda_runtime.h>
#include <cuda_fp16.h>
#include <math.h>
#include <stdint.h>

// Problem dims
#define Q    64
#define SQ   32
#define CC   256
#define SC   256
#define H    768
#define D    128
#define QT   31
#define CT   255
#define QROWS (Q*QT)     // 1984
#define CROWS (CC*CT)    // 65280
#define NROWS (QROWS+CROWS)

// Scratch
__device__ __half g_colh[(size_t)NROWS * D];
__device__ float  g_denom[Q];
__device__ int    g_idx[CC * 256];
__device__ int    g_cnt[CC];
__device__ int    g_qoff[Q + 1];
__device__ int    g_gqidx[QROWS];
__device__ int    g_tile_qs[16], g_tile_qe[16], g_tile_rs[16];
__device__ int    g_ntiles;
__device__ int    g_nun;            // ticket counter; reset by maxsim at sequence end
__device__ int    g_unrows[NROWS];

// ---------------------------------------------------------------------------
// helpers
// ---------------------------------------------------------------------------
__device__ __forceinline__ void mma_tf32(float* c, const uint32_t* a, const uint32_t* b) {
    asm volatile(
        "mma.sync.aligned.m16n8k8.row.col.f32.tf32.tf32.f32 "
        "{%0,%1,%2,%3},{%4,%5,%6,%7},{%8,%9},{%0,%1,%2,%3};\n"
        : "+f"(c[0]), "+f"(c[1]), "+f"(c[2]), "+f"(c[3])
        : "r"(a[0]), "r"(a[1]), "r"(a[2]), "r"(a[3]), "r"(b[0]), "r"(b[1]));
}
__device__ __forceinline__ void mma_f16(float* c, const uint32_t* a, const uint32_t* b) {
    asm volatile(
        "mma.sync.aligned.m16n8k16.row.col.f32.f16.f16.f32 "
        "{%0,%1,%2,%3},{%4,%5,%6,%7},{%8,%9},{%0,%1,%2,%3};\n"
        : "+f"(c[0]), "+f"(c[1]), "+f"(c[2]), "+f"(c[3])
        : "r"(a[0]), "r"(a[1]), "r"(a[2]), "r"(a[3]), "r"(b[0]), "r"(b[1]));
}
__device__ __forceinline__ uint32_t smem_u32(const void* p) {
    uint32_t a;
    asm("{ .reg .u64 t; cvta.to.shared.u64 t, %1; cvt.u32.u64 %0, t; }" : "=r"(a) : "l"(p));
    return a;
}
#define CP_ASYNC16(dst_u32, src_ptr) \
    asm volatile("cp.async.ca.shared.global [%0], [%1], 16;" :: "r"(dst_u32), "l"(src_ptr))
#define CP_COMMIT() asm volatile("cp.async.commit_group;" ::: "memory")
#define CP_WAIT1()  asm volatile("cp.async.wait_group 1;" ::: "memory")
#define CP_WAIT0()  asm volatile("cp.async.wait_group 0;" ::: "memory")

// ---------------------------------------------------------------------------
// Kernel 1: setup — ONE ROLE PER BLOCK (parallel, short critical paths).
// Grid 840: [0,320) pooled | [320,583) unlist | [583,839) compact | 839 prep.
// ---------------------------------------------------------------------------
__global__ void setup_kernel(const float* __restrict__ qh,
                             const float* __restrict__ ch,
                             const float* __restrict__ bias,
                             const int*   __restrict__ qm,
                             const int*   __restrict__ cm,
                             float* __restrict__ out) {
    int b = blockIdx.x, t = threadIdx.x;
    int lane = t & 31, w = t >> 5;

    if (b < 320) {
        // ---- pooled (fp32 exact) ----
        __shared__ float red[8];
        const float* src;
        float mask;
        float* dst;
        if (b < Q) {
            src  = qh + (size_t)b * SQ * H;
            mask = (float)qm[b * SQ];
            dst  = out + Q * CC + (size_t)b * H;
        } else {
            int c = b - Q;
            src  = ch + (size_t)c * SC * H;
            mask = (float)cm[c * SC];
            dst  = out + Q * CC + Q * H + (size_t)c * H;
        }
        float v[3];
        float s = 0.f;
#pragma unroll
        for (int it = 0; it < 3; it++) {
            float x = src[t + it * 256] * mask;
            v[it] = x;
            s += x * x;
        }
#pragma unroll
        for (int o = 16; o; o >>= 1) s += __shfl_xor_sync(0xffffffffu, s, o);
        if (lane == 0) red[w] = s;
        __syncthreads();
        if (t < 8) {
            float ss = red[t];
#pragma unroll
            for (int o = 4; o; o >>= 1) ss += __shfl_xor_sync(0xffu, ss, o);
            if (t == 0) red[0] = ss;
        }
        __syncthreads();
        float inv = 1.f / fmaxf(sqrtf(red[0]), 1e-12f);
#pragma unroll
        for (int it = 0; it < 3; it++) dst[t + it * 256] = v[it] * inv;

    } else if (b < 583) {
        // ---- unlist (ticketed compaction of unmasked rows) ----
        int r = (b - 320) * 256 + t;
        int m = 0;
        if (r < NROWS) {
            if (r < QROWS) { int q = r / QT, i = r % QT; m = qm[q * SQ + i + 1]; }
            else { int rc = r - QROWS; int c = rc / CT, j = rc % CT; m = cm[c * SC + j + 1]; }
        }
        unsigned bal = __ballot_sync(0xffffffffu, m != 0);
        int cnt = __popc(bal);
        int pre = __popc(bal & ((1u << lane) - 1));
        int base = 0;
        if (lane == 0 && cnt) base = atomicAdd(&g_nun, cnt);
        base = __shfl_sync(0xffffffffu, base, 0);
        if (m) g_unrows[base + pre] = r;

    } else if (b < 839) {
        // ---- doc compaction + cvec rep-row write ----
        __shared__ int wcnt[8];
        __shared__ int firstmask;
        __shared__ float s_cr[4];
        int c = b - 583;
        if (t == 0) firstmask = 1 << 30;
        __syncthreads();
        int valid = (t >= 1);
        int m = valid ? cm[c * SC + t] : 0;
        unsigned bal = __ballot_sync(0xffffffffu, m != 0);
        int pre = __popc(bal & ((1u << lane) - 1));
        if (lane == 0) wcnt[w] = __popc(bal);
        if (valid && !m) atomicMin(&firstmask, t);
        __syncthreads();
        int off = 0;
        for (int i = 0; i < w; i++) off += wcnt[i];
        if (valid && m) g_idx[c * 256 + off + pre] = t - 1;
        if (t == 0) {
            int total = 0;
            for (int i = 0; i < 8; i++) total += wcnt[i];
            if (firstmask < 256) { g_idx[c * 256 + total] = firstmask - 1; total++; }
            g_cnt[c] = total;
        }
        float v = (t < D) ? bias[t] : 0.f;
        float sq = v * v;
#pragma unroll
        for (int o = 16; o; o >>= 1) sq += __shfl_xor_sync(0xffffffffu, sq, o);
        if (lane == 0 && t < D) s_cr[w] = sq;
        __syncthreads();
        if (firstmask < 256 && t < D) {
            float tot = s_cr[0] + s_cr[1] + s_cr[2] + s_cr[3];
            float inv = 1.f / fmaxf(sqrtf(tot), 1e-12f);
            size_t row = (size_t)QROWS + (size_t)c * CT + (firstmask - 1);
            g_colh[row * D + t] = __float2half_rn(v * inv);
        }

    } else {
        // ---- q-side prep ----
        __shared__ int s_nu[64];
        __shared__ int s_qoff[65];
        if (t < 64) {
            int nu = 0;
            for (int i = 1; i < SQ; i++) nu += (qm[t * SQ + i] != 0);
            s_nu[t] = nu;
            g_denom[t] = (float)nu;
        }
        __syncthreads();
        if (t == 0) {
            int acc = 0;
            for (int q = 0; q < 64; q++) { s_qoff[q] = acc; acc += s_nu[q]; }
            s_qoff[64] = acc;
            int ntiles = 0, cur = 0;
            while (cur < 64) {
                int qs = cur;
                while (cur < 64 && (s_qoff[cur + 1] - s_qoff[qs]) <= 128) cur++;
                g_tile_qs[ntiles] = qs;
                g_tile_qe[ntiles] = cur;
                g_tile_rs[ntiles] = s_qoff[qs];
                ntiles++;
            }
            g_ntiles = ntiles;
        }
        __syncthreads();
        if (t < 65) g_qoff[t] = s_qoff[t];
        if (t < 64) {
            int pos = s_qoff[t];
            for (int i = 1; i < SQ; i++)
                if (qm[t * SQ + i] != 0) g_gqidx[pos++] = t * QT + i - 1;
        }
    }
}

// ---------------------------------------------------------------------------
// Kernel 2: projection + l2norm over unmasked rows (unchanged — proven).
// ---------------------------------------------------------------------------
#define P_SA 36
#define P_SW 132
#define P_AS_F (128 * P_SA)
#define P_WS_F (32 * P_SW)
#define P_SMEM_FLOATS (2*P_AS_F + 2*P_WS_F + 256 + 128 + 256 + 128 + 128)
#define P_SMEM_BYTES (P_SMEM_FLOATS * 4)

__global__ __launch_bounds__(256) void proj_kernel(const float* __restrict__ qh,
                                                   const float* __restrict__ ch,
                                                   const float* __restrict__ Wm,
                                                   const float* __restrict__ bias) {
    int nun = g_nun;
    if (blockIdx.x * 128 >= nun) return;

    extern __shared__ float psm[];
    float* As0 = psm;
    float* As1 = psm + P_AS_F;
    float* Ws0 = psm + 2 * P_AS_F;
    float* Ws1 = Ws0 + P_WS_F;
    const float** srcp = (const float**)(psm + 2 * P_AS_F + 2 * P_WS_F);
    int*   rowid  = (int*)(srcp + 128);
    float* rowsq  = (float*)(rowid + 128);
    float* invn   = rowsq + 256;
    float* s_bias = invn + 128;

    int t = threadIdx.x;
    int w = t >> 5, lane = t & 31, g = lane >> 2, tg = lane & 3;
    int mw = w & 3, nw = w >> 2;
    int m_warp = mw * 32, n_warp = nw * 64;

    if (t < 128) {
        s_bias[t] = bias[t];
        int idx = blockIdx.x * 128 + t;
        if (idx < nun) {
            int r = g_unrows[idx];
            rowid[t] = r;
            if (r < QROWS) {
                int q = r / QT, i = r % QT;
                srcp[t] = qh + (size_t)(q * SQ + i + 1) * H;
            } else {
                int rc = r - QROWS;
                int c = rc / CT, j = rc % CT;
                srcp[t] = ch + (size_t)(c * SC + j + 1) * H;
            }
        } else {
            rowid[t] = -1;
            srcp[t] = qh;
        }
    }
    __syncthreads();

#define PSTAGE(bufA, bufW, KT) do {                                             \
    _Pragma("unroll")                                                           \
    for (int itc = 0; itc < 4; itc++) {                                         \
        int idx = t + itc * 256;                                                \
        int m = idx >> 3, k4 = idx & 7;                                         \
        CP_ASYNC16(smem_u32((bufA) + m * P_SA + k4 * 4), srcp[m] + (KT) + k4 * 4); \
    }                                                                           \
    _Pragma("unroll")                                                           \
    for (int itc = 0; itc < 4; itc++) {                                         \
        int idx = t + itc * 256;                                                \
        int k = idx >> 5, d4 = idx & 31;                                        \
        CP_ASYNC16(smem_u32((bufW) + k * P_SW + d4 * 4),                        \
                   Wm + (size_t)((KT) + k) * D + d4 * 4);                       \
    }                                                                           \
} while (0)

    PSTAGE(As0, Ws0, 0);
    CP_COMMIT();

    float acc[2][8][4];
#pragma unroll
    for (int mt = 0; mt < 2; mt++)
#pragma unroll
        for (int nt4 = 0; nt4 < 8; nt4++)
#pragma unroll
            for (int i = 0; i < 4; i++) acc[mt][nt4][i] = 0.f;

    for (int it = 0; it < 24; it++) {
        if (it < 23) {
            if (it & 1) PSTAGE(As0, Ws0, (it + 1) * 32);
            else        PSTAGE(As1, Ws1, (it + 1) * 32);
            CP_COMMIT();
            CP_WAIT1();
        } else {
            CP_WAIT0();
        }
        __syncthreads();
        const float* A = (it & 1) ? As1 : As0;
        const float* W = (it & 1) ? Ws1 : Ws0;
#pragma unroll
        for (int ks = 0; ks < 4; ks++) {
            int k0 = ks * 8;
            uint32_t afr[2][4], bfr[8][2];
#pragma unroll
            for (int mt = 0; mt < 2; mt++) {
                int base = m_warp + mt * 16;
                afr[mt][0] = __float_as_uint(A[(base + g)     * P_SA + k0 + tg]);
                afr[mt][1] = __float_as_uint(A[(base + g + 8) * P_SA + k0 + tg]);
                afr[mt][2] = __float_as_uint(A[(base + g)     * P_SA + k0 + tg + 4]);
                afr[mt][3] = __float_as_uint(A[(base + g + 8) * P_SA + k0 + tg + 4]);
            }
#pragma unroll
            for (int nt4 = 0; nt4 < 8; nt4++) {
                int col = n_warp + nt4 * 8 + g;
                bfr[nt4][0] = __float_as_uint(W[(k0 + tg)     * P_SW + col]);
                bfr[nt4][1] = __float_as_uint(W[(k0 + tg + 4) * P_SW + col]);
            }
#pragma unroll
            for (int mt = 0; mt < 2; mt++)
#pragma unroll
                for (int nt4 = 0; nt4 < 8; nt4++)
                    mma_tf32(acc[mt][nt4], afr[mt], bfr[nt4]);
        }
        __syncthreads();
    }

#pragma unroll
    for (int mt = 0; mt < 2; mt++)
#pragma unroll
        for (int nt4 = 0; nt4 < 8; nt4++)
#pragma unroll
            for (int i = 0; i < 4; i++)
                acc[mt][nt4][i] += s_bias[n_warp + nt4 * 8 + 2 * tg + (i & 1)];

    float pr[2][2];
#pragma unroll
    for (int mt = 0; mt < 2; mt++)
#pragma unroll
        for (int h = 0; h < 2; h++) {
            float s = 0.f;
#pragma unroll
            for (int nt4 = 0; nt4 < 8; nt4++) {
                float c0 = acc[mt][nt4][2 * h], c1 = acc[mt][nt4][2 * h + 1];
                s += c0 * c0 + c1 * c1;
            }
            pr[mt][h] = s;
        }
#pragma unroll
    for (int off = 1; off <= 2; off <<= 1) {
#pragma unroll
        for (int mt = 0; mt < 2; mt++)
#pragma unroll
            for (int h = 0; h < 2; h++)
                pr[mt][h] += __shfl_xor_sync(0xffffffffu, pr[mt][h], off);
    }
    if (tg == 0) {
#pragma unroll
        for (int mt = 0; mt < 2; mt++)
#pragma unroll
            for (int h = 0; h < 2; h++)
                rowsq[(m_warp + mt * 16 + g + 8 * h) * 2 + nw] = pr[mt][h];
    }
    __syncthreads();
    if (t < 128) {
        float s = rowsq[t * 2] + rowsq[t * 2 + 1];
        invn[t] = 1.f / fmaxf(sqrtf(s), 1e-12f);
    }
    __syncthreads();

#pragma unroll
    for (int mt = 0; mt < 2; mt++)
#pragma unroll
        for (int h = 0; h < 2; h++) {
            int r = m_warp + mt * 16 + g + 8 * h;
            int grow = rowid[r];
            if (grow >= 0) {
                float inv = invn[r];
                __half* dst = g_colh + (size_t)grow * D;
#pragma unroll
                for (int nt4 = 0; nt4 < 8; nt4++) {
                    int col = n_warp + nt4 * 8 + 2 * tg;
                    *(__half2*)(dst + col) =
                        __floats2half2_rn(acc[mt][nt4][2 * h] * inv,
                                          acc[mt][nt4][2 * h + 1] * inv);
                }
            }
        }
#undef PSTAGE
}

// ---------------------------------------------------------------------------
// Kernel 3: fused maxsim — 256 threads, __launch_bounds__(256,2): 2 CTA/SM.
// 8 warps = 2(M) x 4(N); warp tile 64 x 16-per-N-tile (acc[4][2NT][4]).
// In-block cmax; merged rowmax+segsum epilogue (2 syncs/tile).
// Grid (256, 2): yy=0 tiles [0,ht), yy=1 [ht,ntiles).
// smem ~105.7 KB -> 2 CTA/SM (211 KB < 228); regs capped at 128.
// ---------------------------------------------------------------------------
#define MS_SAH 136
#define MS_SBH 136
#define MSA_HALFS (128 * MS_SAH)
#define MSB_HALFS (256 * MS_SBH)
#define MS_SMEM_BYTES ((MSA_HALFS + MSB_HALFS) * 2 + (4 * 128) * 4 + 256 * 4 + 128 * 4 + 12 * 4)

#define MS_STAGEA(TT_) do {                                                      \
    int rs_ = g_tile_rs[TT_];                                                    \
    int rows_ = g_qoff[g_tile_qe[TT_]] - rs_;                                    \
    int chunks_ = rows_ * 16;                                                    \
    _Pragma("unroll")                                                            \
    for (int j = 0; j < 8; j++) {                                                \
        int idx = t + j * 256;                                                   \
        if (idx < chunks_) {                                                     \
            int m = idx >> 4, k8 = idx & 15;                                     \
            int grow = g_gqidx[rs_ + m];                                         \
            CP_ASYNC16(smem_u32(&Ash[m * MS_SAH + k8 * 8]),                      \
                       g_colh + (size_t)grow * D + k8 * 8);                      \
        }                                                                        \
    }                                                                            \
} while (0)

template <int NT>
__device__ __forceinline__ void ms_body(__half* Ash, const __half* Bsh, float* red,
                                        const float* s_cv, float* s_cm,
                                        float* __restrict__ out,
                                        int t, int c, int tstart, int tend, int nc) {
    int w = t >> 5, lane = t & 31, g = lane >> 2, tg = lane & 3;
    int mw = w & 1, nw = w >> 1;             // 2 M-warps, 4 N-warps
    int m_warp = mw * 64;

    // ---- In-block cmax: thread t handles compacted row t (nc <= 255). ----
    CP_WAIT0();          // B (and first A) landed
    __syncthreads();
    {
        float p = -INFINITY;
        if (t < nc) {
            const __half* row = Bsh + t * MS_SBH;
            float s = 0.f;
#pragma unroll 16
            for (int k = 0; k < 128; k += 2) {
                __half2 h2 = *(const __half2*)(row + k);
                float2 f2 = __half22float2(h2);
                s += s_cv[k] * f2.x + s_cv[k + 1] * f2.y;
            }
            p = s;
        }
#pragma unroll
        for (int o = 16; o; o >>= 1) p = fmaxf(p, __shfl_xor_sync(0xffffffffu, p, o));
        if (lane == 0) s_cm[1 + w] = p;
    }
    __syncthreads();
    if (t == 0) {
        float b = s_cm[1];
        for (int i = 2; i <= 8; i++) b = fmaxf(b, s_cm[i]);
        s_cm[0] = b;
    }
    __syncthreads();
    float cmax = s_cm[0];

    for (int tt = tstart; tt < tend; tt++) {
        CP_WAIT0();
        __syncthreads();    // A ready; also protects red reuse from prev epilogue

        float acc[4][2 * NT][4];
#pragma unroll
        for (int mt = 0; mt < 4; mt++)
#pragma unroll
            for (int j = 0; j < 2 * NT; j++)
#pragma unroll
                for (int k = 0; k < 4; k++) acc[mt][j][k] = 0.f;

#pragma unroll
        for (int ks = 0; ks < 8; ks++) {
            int k0 = ks * 16;
            uint32_t afr[4][4], bfr[2 * NT][2];
#pragma unroll
            for (int mt = 0; mt < 4; mt++) {
                int base = m_warp + mt * 16;
                afr[mt][0] = *(const uint32_t*)&Ash[(base + g)     * MS_SAH + k0 + 2 * tg];
                afr[mt][1] = *(const uint32_t*)&Ash[(base + g + 8) * MS_SAH + k0 + 2 * tg];
                afr[mt][2] = *(const uint32_t*)&Ash[(base + g)     * MS_SAH + k0 + 2 * tg + 8];
                afr[mt][3] = *(const uint32_t*)&Ash[(base + g + 8) * MS_SAH + k0 + 2 * tg + 8];
            }
#pragma unroll
            for (int nt = 0; nt < NT; nt++)
#pragma unroll
                for (int s2 = 0; s2 < 2; s2++) {
                    int n = nt * 64 + nw * 16 + s2 * 8 + g;
                    bfr[nt * 2 + s2][0] = *(const uint32_t*)&Bsh[n * MS_SBH + k0 + 2 * tg];
                    bfr[nt * 2 + s2][1] = *(const uint32_t*)&Bsh[n * MS_SBH + k0 + 2 * tg + 8];
                }
#pragma unroll
            for (int mt = 0; mt < 4; mt++)
#pragma unroll
                for (int j = 0; j < 2 * NT; j++)
                    mma_f16(acc[mt][j], afr[mt], bfr[j]);
        }

        // Row-max over this warp's cols (guard j < nc).
        float rp[4][2];
#pragma unroll
        for (int mt = 0; mt < 4; mt++) { rp[mt][0] = -INFINITY; rp[mt][1] = -INFINITY; }
#pragma unroll
        for (int nt = 0; nt < NT; nt++)
#pragma unroll
            for (int s2 = 0; s2 < 2; s2++)
#pragma unroll
                for (int mt = 0; mt < 4; mt++)
#pragma unroll
                    for (int k = 0; k < 4; k++) {
                        int j = nt * 64 + nw * 16 + s2 * 8 + 2 * tg + (k & 1);
                        if (j < nc)
                            rp[mt][k >> 1] = fmaxf(rp[mt][k >> 1], acc[mt][nt * 2 + s2][k]);
                    }
#pragma unroll
        for (int off = 1; off <= 2; off <<= 1)
#pragma unroll
            for (int mt = 0; mt < 4; mt++)
#pragma unroll
                for (int h = 0; h < 2; h++)
                    rp[mt][h] = fmaxf(rp[mt][h], __shfl_xor_sync(0xffffffffu, rp[mt][h], off));
        if (tg == 0) {
#pragma unroll
            for (int mt = 0; mt < 4; mt++)
#pragma unroll
                for (int h = 0; h < 2; h++)
                    red[nw * 128 + m_warp + mt * 16 + g + 8 * h] = rp[mt][h];
        }
        __syncthreads();

        // Prefetch next A tile — overlaps the epilogue below.
        if (tt + 1 < tend) {
            MS_STAGEA(tt + 1);
            CP_COMMIT();
        }

        // Merged rowmax + per-query segment sum (t < 64, one query each).
        if (t < 64) {
            int qs = g_tile_qs[tt], qe = g_tile_qe[tt];
            int qi = qs + t;
            if (qi < qe) {
                int rs = g_tile_rs[tt];
                int r0 = g_qoff[qi] - rs;
                int r1 = g_qoff[qi + 1] - rs;
                float s = 0.f;
                for (int r = r0; r < r1; r++) {
                    float mx = fmaxf(fmaxf(red[r], red[128 + r]),
                                     fmaxf(red[256 + r], red[384 + r]));
                    s += mx;
                }
                float nu = g_denom[qi];
                out[qi * CC + c] = ((31.f - nu) * cmax + s) / nu;
            }
        }
        // loop-top CP_WAIT0 + __syncthreads guards red reuse
    }
}

__global__ __launch_bounds__(256, 2) void maxsim_kernel(const float* __restrict__ bias,
                                                        float* __restrict__ out) {
    if (blockIdx.x == 0 && blockIdx.y == 0 && threadIdx.x == 0) g_nun = 0;

    extern __shared__ char smc[];
    __half* Ash   = (__half*)smc;
    __half* Bsh   = Ash + MSA_HALFS;
    float* red    = (float*)(Bsh + MSB_HALFS);   // [4][128]
    int*   sidx   = (int*)(red + 4 * 128);       // [256]
    float* s_cv   = (float*)(sidx + 256);        // [128]
    float* s_cm   = s_cv + 128;                  // [12]

    int t  = threadIdx.x;
    int c  = blockIdx.x;
    int yy = blockIdx.y;

    int ntiles = g_ntiles;
    int ht = (ntiles + 1) >> 1;
    int tstart = yy ? ht : 0;
    int tend   = yy ? ntiles : ht;
    if (tstart >= tend) return;

    int nc = g_cnt[c];
    int NT = (nc + 63) >> 6;

    sidx[t] = g_idx[c * 256 + t];
    // cvec (fp32) from bias
    {
        __shared__ float s_cr[4];
        float v = (t < D) ? bias[t] : 0.f;
        float sq = v * v;
#pragma unroll
        for (int o = 16; o; o >>= 1) sq += __shfl_xor_sync(0xffffffffu, sq, o);
        if ((t & 31) == 0 && t < D) s_cr[t >> 5] = sq;
        __syncthreads();    // also publishes sidx
        if (t < D) {
            float tot = s_cr[0] + s_cr[1] + s_cr[2] + s_cr[3];
            s_cv[t] = v / fmaxf(sqrtf(tot), 1e-12f);
        }
    }
    __syncthreads();

    // Gather-stage B once: nc rows x 16 16B-chunks.
    {
        const __half* base = g_colh + (size_t)(QROWS + c * CT) * D;
        int chunks = nc * 16;
#pragma unroll
        for (int j = 0; j < 16; j++) {
            int idx = t + j * 256;
            if (idx < chunks) {
                int n = idx >> 4, k8 = idx & 15;
                CP_ASYNC16(smem_u32(&Bsh[n * MS_SBH + k8 * 8]),
                           base + (size_t)sidx[n] * D + k8 * 8);
            }
        }
    }
    CP_COMMIT();

    MS_STAGEA(tstart);
    CP_COMMIT();

    if (NT == 2)      ms_body<2>(Ash, Bsh, red, s_cv, s_cm, out, t, c, tstart, tend, nc);
    else if (NT == 3) ms_body<3>(Ash, Bsh, red, s_cv, s_cm, out, t, c, tstart, tend, nc);
    else if (NT == 1) ms_body<1>(Ash, Bsh, red, s_cv, s_cm, out, t, c, tstart, tend, nc);
    else              ms_body<4>(Ash, Bsh, red, s_cv, s_cm, out, t, c, tstart, tend, nc);
}

// ---------------------------------------------------------------------------
extern "C" void kernel_launch(void* const* d_in, const int* in_sizes, int n_in,
                              void* d_out, int out_size) {
    const float* qh  = (const float*)d_in[0];
    const float* ch  = (const float*)d_in[1];
    const float* Wm  = (const float*)d_in[2];
    const float* bia = (const float*)d_in[3];
    const int*   qm  = (const int*)d_in[4];
    const int*   cm  = (const int*)d_in[5];
    float* out = (float*)d_out;

    cudaFuncSetAttribute(proj_kernel,
                         cudaFuncAttributeMaxDynamicSharedMemorySize,
                         P_SMEM_BYTES);
    cudaFuncSetAttribute(maxsim_kernel,
                         cudaFuncAttributeMaxDynamicSharedMemorySize,
                         MS_SMEM_BYTES);

    setup_kernel<<<840, 256>>>(qh, ch, bia, qm, cm, out);
    proj_kernel<<<(NROWS + 127) / 128, 256, P_SMEM_BYTES>>>(qh, ch, Wm, bia);
    maxsim_kernel<<<dim3(CC, 2), 256, MS_SMEM_BYTES>>>(bia, out);
}